// round 2
// baseline (speedup 1.0000x reference)
#include <cuda_runtime.h>
#include <cstddef>

#define BB 64
#define TT 512
#define DD 1024
#define NN 64
#define SCORES_ELEMS (BB*TT*NN)
#define TAGS_OFF SCORES_ELEMS
#define LOSS_OFF (SCORES_ELEMS + BB*TT)

#define L2E 1.4426950408889634f
#define LN2 0.6931471805599453f

__device__ float g_logz[BB];
__device__ float g_gold[BB];

__device__ __forceinline__ float fast_ex2(float x){ float r; asm("ex2.approx.ftz.f32 %0, %1;" : "=f"(r) : "f"(x)); return r; }
__device__ __forceinline__ float fast_lg2(float x){ float r; asm("lg2.approx.ftz.f32 %0, %1;" : "=f"(r) : "f"(x)); return r; }

// ---------------------------------------------------------------------------
// GEMM: scores[row][c] = (X[row,:] @ W[:,c] + b[c]) * mask[row]
// 512 CTAs x 256 threads; CTA tile 64 rows x 64 cols, K-chunks of 64.
// ---------------------------------------------------------------------------
__global__ __launch_bounds__(256) void gemm_kernel(
    const float* __restrict__ X, const float* __restrict__ W,
    const float* __restrict__ bias, const int* __restrict__ mask,
    float* __restrict__ out)
{
    __shared__ __align__(16) float As[64][68];
    __shared__ __align__(16) float Ws[64][64];
    const int tid = threadIdx.x;
    const int rowbase = blockIdx.x * 64;
    const int rg = tid >> 4;         // 0..15
    const int cg = tid & 15;         // 0..15
    const int r0 = rg * 4, c0 = cg * 4;

    float acc[4][4];
    #pragma unroll
    for (int i = 0; i < 4; i++)
        #pragma unroll
        for (int c = 0; c < 4; c++) acc[i][c] = 0.f;

    for (int kk = 0; kk < DD; kk += 64) {
        #pragma unroll
        for (int p = 0; p < 4; p++) {
            int idx = tid + p * 256;
            int r = idx >> 4, q = idx & 15;
            float4 v = *(const float4*)&X[(size_t)(rowbase + r) * DD + kk + q * 4];
            *(float4*)&As[r][q * 4] = v;
        }
        #pragma unroll
        for (int p = 0; p < 4; p++) {
            int idx = tid + p * 256;
            int r = idx >> 4, q = idx & 15;
            float4 v = *(const float4*)&W[(size_t)(kk + r) * NN + q * 4];
            *(float4*)&Ws[r][q * 4] = v;
        }
        __syncthreads();
        #pragma unroll
        for (int k = 0; k < 64; k++) {
            float a0 = As[r0 + 0][k];
            float a1 = As[r0 + 1][k];
            float a2 = As[r0 + 2][k];
            float a3 = As[r0 + 3][k];
            float4 w = *(const float4*)&Ws[k][c0];
            acc[0][0] = fmaf(a0, w.x, acc[0][0]); acc[0][1] = fmaf(a0, w.y, acc[0][1]);
            acc[0][2] = fmaf(a0, w.z, acc[0][2]); acc[0][3] = fmaf(a0, w.w, acc[0][3]);
            acc[1][0] = fmaf(a1, w.x, acc[1][0]); acc[1][1] = fmaf(a1, w.y, acc[1][1]);
            acc[1][2] = fmaf(a1, w.z, acc[1][2]); acc[1][3] = fmaf(a1, w.w, acc[1][3]);
            acc[2][0] = fmaf(a2, w.x, acc[2][0]); acc[2][1] = fmaf(a2, w.y, acc[2][1]);
            acc[2][2] = fmaf(a2, w.z, acc[2][2]); acc[2][3] = fmaf(a2, w.w, acc[2][3]);
            acc[3][0] = fmaf(a3, w.x, acc[3][0]); acc[3][1] = fmaf(a3, w.y, acc[3][1]);
            acc[3][2] = fmaf(a3, w.z, acc[3][2]); acc[3][3] = fmaf(a3, w.w, acc[3][3]);
        }
        __syncthreads();
    }
    float4 bv = *(const float4*)&bias[c0];
    #pragma unroll
    for (int i = 0; i < 4; i++) {
        int row = rowbase + r0 + i;
        float mf = (float)mask[row];
        float4 o;
        o.x = (acc[i][0] + bv.x) * mf;
        o.y = (acc[i][1] + bv.y) * mf;
        o.z = (acc[i][2] + bv.z) * mf;
        o.w = (acc[i][3] + bv.w) * mf;
        *(float4*)&out[(size_t)row * NN + c0] = o;
    }
}

// ---------------------------------------------------------------------------
// CRF kernel: blocks 0..63 = log-partition + gold score; 64..127 = Viterbi.
// 128 threads: thread t handles tag j = t>>1, i-half h = t&1 (partner = lane^1).
// ---------------------------------------------------------------------------
struct VitSm {
    unsigned char bp[(TT - 1) * NN];   // 32704 B
    float alpha[NN];
    int   tag[TT];
    int   mk[TT];
};
struct LseSm {
    float alpha[NN];
    float p[NN];
    float redf[4];
    int   redi[4];
    int   lab[TT];
    int   mk[TT];
};
union CrfSm { VitSm v; LseSm l; };

__global__ __launch_bounds__(128) void crf_kernel(
    const float* __restrict__ scores, const int* __restrict__ mask,
    const int* __restrict__ labels, const float* __restrict__ trans,
    const float* __restrict__ startv, const float* __restrict__ endv,
    float* __restrict__ out_tags)
{
    __shared__ __align__(16) CrfSm sm;
    const int tid = threadIdx.x;
    const int j  = tid >> 1;
    const int h  = tid & 1;
    const int i0 = h * 32;

    if (blockIdx.x < BB) {
        // ================= LOG PARTITION + GOLD =================
        const int b = blockIdx.x;
        for (int t = tid; t < TT; t += 128) {
            sm.l.mk[t]  = mask[b * TT + t];
            sm.l.lab[t] = labels[b * TT + t];
        }
        float E[32];
        #pragma unroll
        for (int i = 0; i < 32; i++) E[i] = fast_ex2(trans[(i0 + i) * NN + j] * L2E);
        const float* srow = scores + (size_t)b * TT * NN + j;
        float alpha = 0.f;
        if (h == 0) { alpha = startv[j] + srow[0]; sm.l.alpha[j] = alpha; }
        __syncthreads();

        float emit_next = srow[NN];
        for (int t = 1; t < TT; t++) {
            float emit = emit_next;
            if (t + 1 < TT) emit_next = srow[(size_t)(t + 1) * NN];
            // m need not be the exact max (alpha spread is bounded ~12): use alpha[0]
            float m = sm.l.alpha[0];
            if (h == 0) sm.l.p[j] = fast_ex2((alpha - m) * L2E);
            __syncthreads();
            float s0 = 0.f, s1 = 0.f, s2 = 0.f, s3 = 0.f;
            #pragma unroll
            for (int i = 0; i < 32; i += 4) {
                float4 pv = *(const float4*)&sm.l.p[i0 + i];
                s0 = fmaf(pv.x, E[i + 0], s0);
                s1 = fmaf(pv.y, E[i + 1], s1);
                s2 = fmaf(pv.z, E[i + 2], s2);
                s3 = fmaf(pv.w, E[i + 3], s3);
            }
            float s = (s0 + s1) + (s2 + s3);
            s += __shfl_xor_sync(0xffffffffu, s, 1);   // combine i-halves (adjacent lanes)
            if (h == 0) {
                float na = fmaf(fast_lg2(s), LN2, m) + emit;
                if (sm.l.mk[t]) alpha = na;
                sm.l.alpha[j] = alpha;
            }
            __syncthreads();
        }
        // final logsumexp(alpha + end)
        if (h == 0) sm.l.p[j] = alpha + endv[j];
        __syncthreads();
        if (tid < 32) {
            float a0 = sm.l.p[tid], a1 = sm.l.p[tid + 32];
            float m2 = sm.l.p[0];
            float ss = fast_ex2((a0 - m2) * L2E) + fast_ex2((a1 - m2) * L2E);
            #pragma unroll
            for (int off = 16; off; off >>= 1) ss += __shfl_xor_sync(0xffffffffu, ss, off);
            if (tid == 0) g_logz[b] = fmaf(fast_lg2(ss), LN2, m2);
        }
        // gold score
        float acc = 0.f; int cnt = 0;
        for (int t = tid; t < TT; t += 128) {
            int mkv = sm.l.mk[t];
            int lt = sm.l.lab[t];
            float mf = (float)mkv;
            acc += scores[((size_t)(b * TT + t)) * NN + lt] * mf;
            if (t > 0) acc += trans[sm.l.lab[t - 1] * NN + lt] * mf;
            cnt += mkv;
        }
        #pragma unroll
        for (int off = 16; off; off >>= 1) {
            acc += __shfl_xor_sync(0xffffffffu, acc, off);
            cnt += __shfl_xor_sync(0xffffffffu, cnt, off);
        }
        int w = tid >> 5;
        if ((tid & 31) == 0) { sm.l.redf[w] = acc; sm.l.redi[w] = cnt; }
        __syncthreads();
        if (tid == 0) {
            float a = sm.l.redf[0] + sm.l.redf[1] + sm.l.redf[2] + sm.l.redf[3];
            int c = sm.l.redi[0] + sm.l.redi[1] + sm.l.redi[2] + sm.l.redi[3];
            g_gold[b] = a + startv[sm.l.lab[0]] + endv[sm.l.lab[c - 1]];
        }
    } else {
        // ================= VITERBI =================
        const int b = blockIdx.x - BB;
        for (int t = tid; t < TT; t += 128) sm.v.mk[t] = mask[b * TT + t];
        float Tr[32];
        #pragma unroll
        for (int i = 0; i < 32; i++) Tr[i] = trans[(i0 + i) * NN + j];
        const float* srow = scores + (size_t)b * TT * NN + j;
        float alpha = 0.f;
        if (h == 0) { alpha = startv[j] + srow[0]; sm.v.alpha[j] = alpha; }
        __syncthreads();

        float emit_next = srow[NN];
        for (int t = 1; t < TT; t++) {
            float emit = emit_next;
            if (t + 1 < TT) emit_next = srow[(size_t)(t + 1) * NN];
            // 4 independent max chains to avoid one serial compare chain
            float b0 = -1e30f, b1 = -1e30f, b2 = -1e30f, b3 = -1e30f;
            int id0 = i0, id1 = i0 + 1, id2 = i0 + 2, id3 = i0 + 3;
            #pragma unroll
            for (int i = 0; i < 32; i += 4) {
                float4 av = *(const float4*)&sm.v.alpha[i0 + i];
                float v0 = av.x + Tr[i + 0];
                float v1 = av.y + Tr[i + 1];
                float v2 = av.z + Tr[i + 2];
                float v3 = av.w + Tr[i + 3];
                if (v0 > b0) { b0 = v0; id0 = i0 + i + 0; }
                if (v1 > b1) { b1 = v1; id1 = i0 + i + 1; }
                if (v2 > b2) { b2 = v2; id2 = i0 + i + 2; }
                if (v3 > b3) { b3 = v3; id3 = i0 + i + 3; }
            }
            // combine chains, tie -> smallest index (matches jnp.argmax "first")
            float best = b0; int bi = id0;
            if (b1 > best || (b1 == best && id1 < bi)) { best = b1; bi = id1; }
            if (b2 > best || (b2 == best && id2 < bi)) { best = b2; bi = id2; }
            if (b3 > best || (b3 == best && id3 < bi)) { best = b3; bi = id3; }
            float vo = __shfl_xor_sync(0xffffffffu, best, 1);
            int   io = __shfl_xor_sync(0xffffffffu, bi, 1);
            if (vo > best || (vo == best && io < bi)) { best = vo; bi = io; }
            __syncthreads();
            if (h == 0) {
                int mkv = sm.v.mk[t];
                sm.v.bp[(t - 1) * NN + j] = (unsigned char)(mkv ? bi : j);
                if (mkv) alpha = best + emit;
                sm.v.alpha[j] = alpha;
            }
            __syncthreads();
        }
        // backtrace (in shared)
        if (tid == 0) {
            float bestf = -1e30f; int cur = 0;
            for (int jj = 0; jj < NN; jj++) {
                float v = sm.v.alpha[jj] + endv[jj];
                if (v > bestf) { bestf = v; cur = jj; }
            }
            sm.v.tag[TT - 1] = cur;
            for (int t = TT - 1; t >= 1; t--) {
                cur = sm.v.bp[(t - 1) * NN + cur];
                sm.v.tag[t - 1] = cur;
            }
        }
        __syncthreads();
        for (int t = tid; t < TT; t += 128)
            out_tags[b * TT + t] = (float)(sm.v.tag[t] * sm.v.mk[t]);
    }
}

// ---------------------------------------------------------------------------
// Loss = mean(log_z - gold)
// ---------------------------------------------------------------------------
__global__ void loss_kernel(float* __restrict__ out_loss) {
    int l = threadIdx.x;  // 32 threads
    float v = (g_logz[l] - g_gold[l]) + (g_logz[l + 32] - g_gold[l + 32]);
    #pragma unroll
    for (int off = 16; off; off >>= 1) v += __shfl_xor_sync(0xffffffffu, v, off);
    if (l == 0) out_loss[0] = v * (1.0f / 64.0f);
}

extern "C" void kernel_launch(void* const* d_in, const int* in_sizes, int n_in,
                              void* d_out, int out_size) {
    const float* X      = (const float*)d_in[0];
    const int*   mask   = (const int*)d_in[1];
    const int*   labels = (const int*)d_in[2];
    const float* W      = (const float*)d_in[3];
    const float* bias   = (const float*)d_in[4];
    const float* trans  = (const float*)d_in[5];
    const float* startv = (const float*)d_in[6];
    const float* endv   = (const float*)d_in[7];
    float* out = (float*)d_out;

    gemm_kernel<<<512, 256>>>(X, W, bias, mask, out);
    crf_kernel<<<128, 128>>>(out, mask, labels, trans, startv, endv, out + TAGS_OFF);
    loss_kernel<<<1, 32>>>(out + LOSS_OFF);
}

// round 3
// speedup vs baseline: 1.0403x; 1.0403x over previous
#include <cuda_runtime.h>
#include <cstddef>

#define BB 64
#define TT 512
#define DD 1024
#define NN 64
#define SCORES_ELEMS (BB*TT*NN)
#define TAGS_OFF SCORES_ELEMS
#define LOSS_OFF (SCORES_ELEMS + BB*TT)

#define L2E 1.4426950408889634f
#define LN2 0.6931471805599453f

__device__ float g_logz[BB];
__device__ float g_gold[BB];

__device__ __forceinline__ float fast_ex2(float x){ float r; asm("ex2.approx.ftz.f32 %0, %1;" : "=f"(r) : "f"(x)); return r; }
__device__ __forceinline__ float fast_lg2(float x){ float r; asm("lg2.approx.ftz.f32 %0, %1;" : "=f"(r) : "f"(x)); return r; }

typedef unsigned long long ull;
__device__ __forceinline__ ull pk2(float x, float y){ ull r; asm("mov.b64 %0, {%1,%2};" : "=l"(r) : "f"(x), "f"(y)); return r; }
__device__ __forceinline__ void upk2(ull v, float& x, float& y){ asm("mov.b64 {%0,%1}, %2;" : "=f"(x), "=f"(y) : "l"(v)); }
__device__ __forceinline__ ull ffma2(ull a, ull b, ull c){ ull d; asm("fma.rn.f32x2 %0, %1, %2, %3;" : "=l"(d) : "l"(a), "l"(b), "l"(c)); return d; }

__device__ __forceinline__ void bar64(){ asm volatile("bar.sync 1, 64;" ::: "memory"); }

// ---------------------------------------------------------------------------
// GEMM with f32x2 dual-FMA: 256 CTAs x 128 threads, tile 128x64, 8x8/thread.
// As stored k-major (transposed on store); Ws natural [k][c] so a ulonglong2
// load gives two packed column-pairs. 'a' replicated into both f32x2 halves
// via mov.b64 on the ALU pipe (overlaps FMA pipe).
// ---------------------------------------------------------------------------
#define KC 32
#define NCHUNK (DD/KC)

__global__ __launch_bounds__(128, 3) void gemm_f32x2_kernel(
    const float* __restrict__ X, const float* __restrict__ W,
    const float* __restrict__ bias, const int* __restrict__ mask,
    float* __restrict__ out)
{
    __shared__ __align__(16) float As[2][KC][128];   // 32768 B
    __shared__ __align__(16) float Ws[2][KC][64];    // 16384 B

    const int tid = threadIdx.x;
    const int rg = tid >> 3;        // 0..15
    const int cg = tid & 7;         // 0..7
    const int r8 = rg * 8, c8 = cg * 8;
    const int rowbase = blockIdx.x * 128;

    const float* Xrow = X + (size_t)(rowbase + tid) * DD;
    const int kr = tid >> 2;            // 0..31
    const int wsoff = (tid & 3) * 16;   // 0,16,32,48

    float4 xa[8], wb[4];

    ull acc[8][4];
    #pragma unroll
    for (int r = 0; r < 8; r++)
        #pragma unroll
        for (int p = 0; p < 4; p++) acc[r][p] = 0ULL;

    // prologue: load + store chunk 0
    #pragma unroll
    for (int q = 0; q < 8; q++) xa[q] = *(const float4*)&Xrow[q * 4];
    #pragma unroll
    for (int e = 0; e < 4; e++) wb[e] = *(const float4*)&W[(size_t)kr * NN + wsoff + e * 4];
    #pragma unroll
    for (int q = 0; q < 8; q++) {
        As[0][q*4+0][tid] = xa[q].x; As[0][q*4+1][tid] = xa[q].y;
        As[0][q*4+2][tid] = xa[q].z; As[0][q*4+3][tid] = xa[q].w;
    }
    #pragma unroll
    for (int e = 0; e < 4; e++) *(float4*)&Ws[0][kr][wsoff + e * 4] = wb[e];
    __syncthreads();

    for (int c = 0; c < NCHUNK; c++) {
        if (c + 1 < NCHUNK) {
            const int kk = (c + 1) * KC;
            #pragma unroll
            for (int q = 0; q < 8; q++) xa[q] = *(const float4*)&Xrow[kk + q * 4];
            #pragma unroll
            for (int e = 0; e < 4; e++) wb[e] = *(const float4*)&W[(size_t)(kk + kr) * NN + wsoff + e * 4];
        }
        const int buf = c & 1;
        #pragma unroll 8
        for (int k = 0; k < KC; k++) {
            float4 a0 = *(const float4*)&As[buf][k][r8];
            float4 a1 = *(const float4*)&As[buf][k][r8 + 4];
            ulonglong2 w0 = *(const ulonglong2*)&Ws[buf][k][c8];
            ulonglong2 w1 = *(const ulonglong2*)&Ws[buf][k][c8 + 4];
            ull A[8];
            A[0] = pk2(a0.x, a0.x); A[1] = pk2(a0.y, a0.y);
            A[2] = pk2(a0.z, a0.z); A[3] = pk2(a0.w, a0.w);
            A[4] = pk2(a1.x, a1.x); A[5] = pk2(a1.y, a1.y);
            A[6] = pk2(a1.z, a1.z); A[7] = pk2(a1.w, a1.w);
            #pragma unroll
            for (int r = 0; r < 8; r++) {
                acc[r][0] = ffma2(A[r], w0.x, acc[r][0]);
                acc[r][1] = ffma2(A[r], w0.y, acc[r][1]);
                acc[r][2] = ffma2(A[r], w1.x, acc[r][2]);
                acc[r][3] = ffma2(A[r], w1.y, acc[r][3]);
            }
        }
        __syncthreads();
        if (c + 1 < NCHUNK) {
            const int nb = (c + 1) & 1;
            #pragma unroll
            for (int q = 0; q < 8; q++) {
                As[nb][q*4+0][tid] = xa[q].x; As[nb][q*4+1][tid] = xa[q].y;
                As[nb][q*4+2][tid] = xa[q].z; As[nb][q*4+3][tid] = xa[q].w;
            }
            #pragma unroll
            for (int e = 0; e < 4; e++) *(float4*)&Ws[nb][kr][wsoff + e * 4] = wb[e];
            __syncthreads();
        }
    }

    float bs[8];
    #pragma unroll
    for (int e = 0; e < 8; e++) bs[e] = bias[c8 + e];
    #pragma unroll
    for (int r = 0; r < 8; r++) {
        const int row = rowbase + r8 + r;
        const float mf = (float)mask[row];
        float v[8];
        upk2(acc[r][0], v[0], v[1]); upk2(acc[r][1], v[2], v[3]);
        upk2(acc[r][2], v[4], v[5]); upk2(acc[r][3], v[6], v[7]);
        float4 o0, o1;
        o0.x = (v[0]+bs[0])*mf; o0.y = (v[1]+bs[1])*mf; o0.z = (v[2]+bs[2])*mf; o0.w = (v[3]+bs[3])*mf;
        o1.x = (v[4]+bs[4])*mf; o1.y = (v[5]+bs[5])*mf; o1.z = (v[6]+bs[6])*mf; o1.w = (v[7]+bs[7])*mf;
        *(float4*)&out[(size_t)row * NN + c8]     = o0;
        *(float4*)&out[(size_t)row * NN + c8 + 4] = o1;
    }
}

// ---------------------------------------------------------------------------
// CRF kernel: blocks 0..63 = log-partition + gold (64 active threads, 1/tag,
// ONE named bar per step); blocks 64..127 = Viterbi (128 threads, 2/tag,
// ONE __syncthreads per step via ping-pong alpha).
// ---------------------------------------------------------------------------
struct VitSm {
    unsigned char bp[(TT - 1) * NN];   // 32704 B
    float alphaS[2][NN];
    int   mk[TT];
    int   tag[TT];
};
struct LseSm {
    float pS[2][NN];
    float mS[2];
    float redf[2];
    int   redi[2];
    int   mk[TT];
    int   lab[TT];
};
union CrfSm { VitSm v; LseSm l; };

__global__ __launch_bounds__(128) void crf_kernel(
    const float* __restrict__ scores, const int* __restrict__ mask,
    const int* __restrict__ labels, const float* __restrict__ trans,
    const float* __restrict__ startv, const float* __restrict__ endv,
    float* __restrict__ out_tags)
{
    __shared__ __align__(16) CrfSm sm;
    const int tid = threadIdx.x;

    if (blockIdx.x < BB) {
        // ================= LOG PARTITION + GOLD (threads 0..63) =============
        if (tid >= 64) return;
        const int b = blockIdx.x;
        const int j = tid;

        for (int t = j; t < TT; t += 64) {
            sm.l.mk[t]  = mask[b * TT + t];
            sm.l.lab[t] = labels[b * TT + t];
        }
        float E[NN];
        #pragma unroll
        for (int i = 0; i < NN; i++) E[i] = fast_ex2(trans[i * NN + j] * L2E);

        const float* srow = scores + (size_t)b * TT * NN + j;
        float alpha = startv[j] + srow[0];
        const float m0 = startv[0] + scores[(size_t)b * TT * NN]; // alpha0 of tag 0
        float Mprev = m0;
        sm.l.pS[0][j] = fast_ex2((alpha - m0) * L2E);
        if (j == 0) sm.l.mS[0] = m0;

        float ecur = srow[NN];
        float enext = srow[2 * NN];
        bar64();

        for (int t = 1; t < TT; t++) {
            const int pb = (t - 1) & 1, cb = t & 1;
            const float mNew = sm.l.mS[pb];
            float s0 = 0.f, s1 = 0.f, s2 = 0.f, s3 = 0.f;
            float s4 = 0.f, s5 = 0.f, s6 = 0.f, s7 = 0.f;
            #pragma unroll
            for (int i = 0; i < NN; i += 8) {
                float4 pa = *(const float4*)&sm.l.pS[pb][i];
                float4 pc = *(const float4*)&sm.l.pS[pb][i + 4];
                s0 = fmaf(pa.x, E[i + 0], s0); s1 = fmaf(pa.y, E[i + 1], s1);
                s2 = fmaf(pa.z, E[i + 2], s2); s3 = fmaf(pa.w, E[i + 3], s3);
                s4 = fmaf(pc.x, E[i + 4], s4); s5 = fmaf(pc.y, E[i + 5], s5);
                s6 = fmaf(pc.z, E[i + 6], s6); s7 = fmaf(pc.w, E[i + 7], s7);
            }
            float s = ((s0 + s1) + (s2 + s3)) + ((s4 + s5) + (s6 + s7));
            float cand = fmaf(fast_lg2(s), LN2, Mprev) + ecur;
            if (sm.l.mk[t]) alpha = cand;
            sm.l.pS[cb][j] = fast_ex2((alpha - mNew) * L2E);
            if (j == 0) sm.l.mS[cb] = alpha;
            Mprev = mNew;
            ecur = enext;
            if (t + 2 < TT) enext = srow[(size_t)(t + 2) * NN];
            bar64();
        }
        // final logsumexp(alpha + end)
        sm.l.pS[0][j] = alpha + endv[j];
        bar64();
        if (tid < 32) {
            float a0 = sm.l.pS[0][tid], a1 = sm.l.pS[0][tid + 32];
            float m2 = sm.l.pS[0][0];
            float ss = fast_ex2((a0 - m2) * L2E) + fast_ex2((a1 - m2) * L2E);
            #pragma unroll
            for (int off = 16; off; off >>= 1) ss += __shfl_xor_sync(0xffffffffu, ss, off);
            if (tid == 0) g_logz[b] = fmaf(fast_lg2(ss), LN2, m2);
        }
        // gold score
        float acc = 0.f; int cnt = 0;
        for (int t = tid; t < TT; t += 64) {
            const int mkv = sm.l.mk[t];
            const int lt = sm.l.lab[t];
            const float mf = (float)mkv;
            acc += scores[((size_t)(b * TT + t)) * NN + lt] * mf;
            if (t > 0) acc += trans[sm.l.lab[t - 1] * NN + lt] * mf;
            cnt += mkv;
        }
        #pragma unroll
        for (int off = 16; off; off >>= 1) {
            acc += __shfl_xor_sync(0xffffffffu, acc, off);
            cnt += __shfl_xor_sync(0xffffffffu, cnt, off);
        }
        if ((tid & 31) == 0) { sm.l.redf[tid >> 5] = acc; sm.l.redi[tid >> 5] = cnt; }
        bar64();
        if (tid == 0) {
            float a = sm.l.redf[0] + sm.l.redf[1];
            int c = sm.l.redi[0] + sm.l.redi[1];
            g_gold[b] = a + startv[sm.l.lab[0]] + endv[sm.l.lab[c - 1]];
        }
    } else {
        // ================= VITERBI (128 threads, 2/tag) =====================
        const int b = blockIdx.x - BB;
        const int j = tid >> 1;
        const int h = tid & 1;
        const int i0 = h * 32;

        for (int t = tid; t < TT; t += 128) sm.v.mk[t] = mask[b * TT + t];
        float Tr[32];
        #pragma unroll
        for (int i = 0; i < 32; i++) Tr[i] = trans[(i0 + i) * NN + j];

        const float* srow = scores + (size_t)b * TT * NN + j;
        float alpha = 0.f;
        if (h == 0) { alpha = startv[j] + srow[0]; sm.v.alphaS[0][j] = alpha; }
        float ecur = srow[NN];
        float enext = srow[2 * NN];
        __syncthreads();

        for (int t = 1; t < TT; t++) {
            const int pb = (t - 1) & 1, cb = t & 1;
            float bv[8]; int bx[8];
            #pragma unroll
            for (int c = 0; c < 8; c++) {
                float4 av = *(const float4*)&sm.v.alphaS[pb][i0 + c * 4];
                float v0 = av.x + Tr[c*4+0];
                float v1 = av.y + Tr[c*4+1];
                float v2 = av.z + Tr[c*4+2];
                float v3 = av.w + Tr[c*4+3];
                float cbv = v0; int ci = i0 + c*4;
                if (v1 > cbv) { cbv = v1; ci = i0 + c*4 + 1; }
                if (v2 > cbv) { cbv = v2; ci = i0 + c*4 + 2; }
                if (v3 > cbv) { cbv = v3; ci = i0 + c*4 + 3; }
                bv[c] = cbv; bx[c] = ci;
            }
            float best = bv[0]; int bi = bx[0];
            #pragma unroll
            for (int c = 1; c < 8; c++)
                if (bv[c] > best || (bv[c] == best && bx[c] < bi)) { best = bv[c]; bi = bx[c]; }
            const float vo = __shfl_xor_sync(0xffffffffu, best, 1);
            const int   io = __shfl_xor_sync(0xffffffffu, bi, 1);
            if (vo > best || (vo == best && io < bi)) { best = vo; bi = io; }
            if (h == 0) {
                const int mkv = sm.v.mk[t];
                sm.v.bp[(t - 1) * NN + j] = (unsigned char)(mkv ? bi : j);
                if (mkv) alpha = best + ecur;
                sm.v.alphaS[cb][j] = alpha;
            }
            ecur = enext;
            if (t + 2 < TT) enext = srow[(size_t)(t + 2) * NN];
            __syncthreads();
        }
        // backtrace
        if (tid == 0) {
            const int fb = (TT - 1) & 1;
            float bestf = -1e30f; int cur = 0;
            for (int jj = 0; jj < NN; jj++) {
                float v = sm.v.alphaS[fb][jj] + endv[jj];
                if (v > bestf) { bestf = v; cur = jj; }
            }
            sm.v.tag[TT - 1] = cur;
            for (int t = TT - 1; t >= 1; t--) {
                cur = sm.v.bp[(t - 1) * NN + cur];
                sm.v.tag[t - 1] = cur;
            }
        }
        __syncthreads();
        for (int t = tid; t < TT; t += 128)
            out_tags[b * TT + t] = (float)(sm.v.tag[t] * sm.v.mk[t]);
    }
}

// ---------------------------------------------------------------------------
// Loss = mean(log_z - gold)
// ---------------------------------------------------------------------------
__global__ void loss_kernel(float* __restrict__ out_loss) {
    int l = threadIdx.x;  // 32 threads
    float v = (g_logz[l] - g_gold[l]) + (g_logz[l + 32] - g_gold[l + 32]);
    #pragma unroll
    for (int off = 16; off; off >>= 1) v += __shfl_xor_sync(0xffffffffu, v, off);
    if (l == 0) out_loss[0] = v * (1.0f / 64.0f);
}

extern "C" void kernel_launch(void* const* d_in, const int* in_sizes, int n_in,
                              void* d_out, int out_size) {
    const float* X      = (const float*)d_in[0];
    const int*   mask   = (const int*)d_in[1];
    const int*   labels = (const int*)d_in[2];
    const float* W      = (const float*)d_in[3];
    const float* bias   = (const float*)d_in[4];
    const float* trans  = (const float*)d_in[5];
    const float* startv = (const float*)d_in[6];
    const float* endv   = (const float*)d_in[7];
    float* out = (float*)d_out;

    gemm_f32x2_kernel<<<256, 128>>>(X, W, bias, mask, out);
    crf_kernel<<<128, 128>>>(out, mask, labels, trans, startv, endv, out + TAGS_OFF);
    loss_kernel<<<1, 32>>>(out + LOSS_OFF);
}

// round 4
// speedup vs baseline: 1.0490x; 1.0084x over previous
#include <cuda_runtime.h>
#include <cstddef>

#define BB 64
#define TT 512
#define DD 1024
#define NN 64
#define SCORES_ELEMS (BB*TT*NN)
#define TAGS_OFF SCORES_ELEMS
#define LOSS_OFF (SCORES_ELEMS + BB*TT)

#define L2E 1.4426950408889634f
#define LN2 0.6931471805599453f

__device__ float g_logz[BB];
__device__ float g_gold[BB];
__device__ __align__(16) float g_part[SCORES_ELEMS];   // split-K partial (8MB)

__device__ __forceinline__ float fast_ex2(float x){ float r; asm("ex2.approx.ftz.f32 %0, %1;" : "=f"(r) : "f"(x)); return r; }
__device__ __forceinline__ float fast_lg2(float x){ float r; asm("lg2.approx.ftz.f32 %0, %1;" : "=f"(r) : "f"(x)); return r; }

typedef unsigned long long ull;
__device__ __forceinline__ ull pk2(float x, float y){ ull r; asm("mov.b64 %0, {%1,%2};" : "=l"(r) : "f"(x), "f"(y)); return r; }
__device__ __forceinline__ void upk2(ull v, float& x, float& y){ asm("mov.b64 {%0,%1}, %2;" : "=f"(x), "=f"(y) : "l"(v)); }
__device__ __forceinline__ ull ffma2(ull a, ull b, ull c){ ull d; asm("fma.rn.f32x2 %0, %1, %2, %3;" : "=l"(d) : "l"(a), "l"(b), "l"(c)); return d; }

__device__ __forceinline__ void bar1_64(){ asm volatile("bar.sync 1, 64;" ::: "memory"); }
__device__ __forceinline__ void bar2_64(){ asm volatile("bar.sync 2, 64;" ::: "memory"); }

// ---------------------------------------------------------------------------
// Split-K GEMM with f32x2 dual-FMA.
// grid = 512: blockIdx.x = rowtile*2 + split. Each CTA: 128 rows x 64 cols,
// K-range [split*512, split*512+512). Raw partial sums (no bias/mask):
// split 0 -> out, split 1 -> g_part. One __syncthreads per K-chunk.
// ---------------------------------------------------------------------------
#define KC 32
#define KSPLIT 512
#define NCHUNK (KSPLIT/KC)

__global__ __launch_bounds__(128, 3) void gemm_f32x2_kernel(
    const float* __restrict__ X, const float* __restrict__ W,
    float* __restrict__ out)
{
    __shared__ __align__(16) float As[2][KC][128];   // 32768 B
    __shared__ __align__(16) float Ws[2][KC][64];    // 16384 B

    const int tid = threadIdx.x;
    const int split = blockIdx.x & 1;
    const int rowtile = blockIdx.x >> 1;
    const int rowbase = rowtile * 128;
    const int kbase = split * KSPLIT;

    const int rg = tid >> 3;        // 0..15
    const int cg = tid & 7;         // 0..7
    const int r8 = rg * 8, c8 = cg * 8;

    const float* Xrow = X + (size_t)(rowbase + tid) * DD + kbase;
    const int kr = tid >> 2;            // 0..31
    const int wsoff = (tid & 3) * 16;   // 0,16,32,48
    const float* Wbase = W + (size_t)(kbase + kr) * NN + wsoff;

    float4 xa[8], wb[4];

    ull acc[8][4];
    #pragma unroll
    for (int r = 0; r < 8; r++)
        #pragma unroll
        for (int p = 0; p < 4; p++) acc[r][p] = 0ULL;

    // prologue: chunk 0
    #pragma unroll
    for (int q = 0; q < 8; q++) xa[q] = *(const float4*)&Xrow[q * 4];
    #pragma unroll
    for (int e = 0; e < 4; e++) wb[e] = *(const float4*)&Wbase[e * 4];
    #pragma unroll
    for (int q = 0; q < 8; q++) {
        As[0][q*4+0][tid] = xa[q].x; As[0][q*4+1][tid] = xa[q].y;
        As[0][q*4+2][tid] = xa[q].z; As[0][q*4+3][tid] = xa[q].w;
    }
    #pragma unroll
    for (int e = 0; e < 4; e++) *(float4*)&Ws[0][kr][wsoff + e * 4] = wb[e];
    __syncthreads();

    for (int c = 0; c < NCHUNK; c++) {
        if (c + 1 < NCHUNK) {
            const int kk = (c + 1) * KC;
            #pragma unroll
            for (int q = 0; q < 8; q++) xa[q] = *(const float4*)&Xrow[kk + q * 4];
            #pragma unroll
            for (int e = 0; e < 4; e++) wb[e] = *(const float4*)&Wbase[(size_t)kk * NN + e * 4];
        }
        const int buf = c & 1;
        #pragma unroll 8
        for (int k = 0; k < KC; k++) {
            float4 a0 = *(const float4*)&As[buf][k][r8];
            float4 a1 = *(const float4*)&As[buf][k][r8 + 4];
            ulonglong2 w0 = *(const ulonglong2*)&Ws[buf][k][c8];
            ulonglong2 w1 = *(const ulonglong2*)&Ws[buf][k][c8 + 4];
            ull A[8];
            A[0] = pk2(a0.x, a0.x); A[1] = pk2(a0.y, a0.y);
            A[2] = pk2(a0.z, a0.z); A[3] = pk2(a0.w, a0.w);
            A[4] = pk2(a1.x, a1.x); A[5] = pk2(a1.y, a1.y);
            A[6] = pk2(a1.z, a1.z); A[7] = pk2(a1.w, a1.w);
            #pragma unroll
            for (int r = 0; r < 8; r++) {
                acc[r][0] = ffma2(A[r], w0.x, acc[r][0]);
                acc[r][1] = ffma2(A[r], w0.y, acc[r][1]);
                acc[r][2] = ffma2(A[r], w1.x, acc[r][2]);
                acc[r][3] = ffma2(A[r], w1.y, acc[r][3]);
            }
        }
        if (c + 1 < NCHUNK) {
            const int nb = (c + 1) & 1;
            // safe: buffer nb was last READ in iteration c-1, all readers passed
            // the sync at the end of c-1.
            #pragma unroll
            for (int q = 0; q < 8; q++) {
                As[nb][q*4+0][tid] = xa[q].x; As[nb][q*4+1][tid] = xa[q].y;
                As[nb][q*4+2][tid] = xa[q].z; As[nb][q*4+3][tid] = xa[q].w;
            }
            #pragma unroll
            for (int e = 0; e < 4; e++) *(float4*)&Ws[nb][kr][wsoff + e * 4] = wb[e];
            __syncthreads();
        }
    }

    float* dst = split ? g_part : out;
    #pragma unroll
    for (int r = 0; r < 8; r++) {
        const int row = rowbase + r8 + r;
        float v[8];
        upk2(acc[r][0], v[0], v[1]); upk2(acc[r][1], v[2], v[3]);
        upk2(acc[r][2], v[4], v[5]); upk2(acc[r][3], v[6], v[7]);
        float4 o0 = { v[0], v[1], v[2], v[3] };
        float4 o1 = { v[4], v[5], v[6], v[7] };
        *(float4*)&dst[(size_t)row * NN + c8]     = o0;
        *(float4*)&dst[(size_t)row * NN + c8 + 4] = o1;
    }
}

// out = (out + g_part + bias) * mask   (524288 float4s)
__global__ __launch_bounds__(256) void reduce_kernel(
    const float* __restrict__ bias, const int* __restrict__ mask,
    float* __restrict__ out)
{
    const int i = blockIdx.x * 256 + threadIdx.x;     // float4 index
    float4 a = ((const float4*)out)[i];
    float4 p = ((const float4*)g_part)[i];
    const int row = i >> 4;
    const float mf = (float)mask[row];
    const int c4 = (i & 15) * 4;
    float4 bv = *(const float4*)&bias[c4];
    float4 o;
    o.x = (a.x + p.x + bv.x) * mf;
    o.y = (a.y + p.y + bv.y) * mf;
    o.z = (a.z + p.z + bv.z) * mf;
    o.w = (a.w + p.w + bv.w) * mf;
    ((float4*)out)[i] = o;
}

// ---------------------------------------------------------------------------
// CRF kernel: blocks 0..63 = log-partition (threads 0-63, bar1) with gold
// score computed CONCURRENTLY by threads 64-127 (bar2).
// Blocks 64..127 = Viterbi (128 threads).
// Mask bits live in registers (ballot), removing LDS from the step path.
// ---------------------------------------------------------------------------
struct VitSm {
    unsigned char bp[(TT - 1) * NN];   // 32704 B
    float alphaS[2][NN];
    int   tag[TT];
};
struct LseSm {
    float pS[2][NN];
    float redf[2];
    int   redi[2];
};
union CrfSm { VitSm v; LseSm l; };

__global__ __launch_bounds__(128) void crf_kernel(
    const float* __restrict__ scores, const int* __restrict__ mask,
    const int* __restrict__ labels, const float* __restrict__ trans,
    const float* __restrict__ startv, const float* __restrict__ endv,
    float* __restrict__ out_tags)
{
    __shared__ __align__(16) CrfSm sm;
    const int tid = threadIdx.x;

    if (blockIdx.x < BB) {
        const int b = blockIdx.x;
        if (tid < 64) {
            // ============ LOG PARTITION (threads 0..63, 1 thread/tag) =======
            const int j = tid;
            // mask bits -> registers (both warps compute identical words)
            unsigned mkb[TT/32];
            #pragma unroll
            for (int w = 0; w < TT/32; w++)
                mkb[w] = __ballot_sync(0xffffffffu, mask[b * TT + w * 32 + (tid & 31)] != 0);

            float E[NN];
            #pragma unroll
            for (int i = 0; i < NN; i++) E[i] = fast_ex2(trans[i * NN + j] * L2E);

            const float* srow = scores + (size_t)b * TT * NN + j;
            float alpha = startv[j] + srow[0];
            const float m0 = startv[0] + scores[(size_t)b * TT * NN]; // alpha_0(tag0)
            float Mref = m0;                       // reference of current pS buffer
            sm.l.pS[0][j] = fast_ex2((alpha - m0) * L2E);

            float ecur = srow[NN];
            float enext = srow[2 * NN];
            bar1_64();

            for (int t = 1; t < TT; t++) {
                const int pb = (t - 1) & 1, cb = t & 1;
                float p0 = sm.l.pS[pb][0];
                const float mNew = fmaf(fast_lg2(p0), LN2, Mref); // = alpha0^(t-1)
                float s0 = 0.f, s1 = 0.f, s2 = 0.f, s3 = 0.f;
                float s4 = 0.f, s5 = 0.f, s6 = 0.f, s7 = 0.f;
                #pragma unroll
                for (int i = 0; i < NN; i += 8) {
                    float4 pa = *(const float4*)&sm.l.pS[pb][i];
                    float4 pc = *(const float4*)&sm.l.pS[pb][i + 4];
                    s0 = fmaf(pa.x, E[i + 0], s0); s1 = fmaf(pa.y, E[i + 1], s1);
                    s2 = fmaf(pa.z, E[i + 2], s2); s3 = fmaf(pa.w, E[i + 3], s3);
                    s4 = fmaf(pc.x, E[i + 4], s4); s5 = fmaf(pc.y, E[i + 5], s5);
                    s6 = fmaf(pc.z, E[i + 6], s6); s7 = fmaf(pc.w, E[i + 7], s7);
                }
                float s = ((s0 + s1) + (s2 + s3)) + ((s4 + s5) + (s6 + s7));
                float cand = fmaf(fast_lg2(s), LN2, Mref) + ecur;
                const int bit = (mkb[t >> 5] >> (t & 31)) & 1;
                if (bit) alpha = cand;
                sm.l.pS[cb][j] = fast_ex2((alpha - mNew) * L2E);
                Mref = mNew;
                ecur = enext;
                if (t + 2 < TT) enext = srow[(size_t)(t + 2) * NN];
                bar1_64();
            }
            // final logsumexp(alpha + end)
            sm.l.pS[0][j] = alpha + endv[j];
            bar1_64();
            if (tid < 32) {
                float a0 = sm.l.pS[0][tid], a1 = sm.l.pS[0][tid + 32];
                float m2 = sm.l.pS[0][0];
                float ss = fast_ex2((a0 - m2) * L2E) + fast_ex2((a1 - m2) * L2E);
                #pragma unroll
                for (int off = 16; off; off >>= 1) ss += __shfl_xor_sync(0xffffffffu, ss, off);
                if (tid == 0) g_logz[b] = fmaf(fast_lg2(ss), LN2, m2);
            }
        } else {
            // ============ GOLD SCORE (threads 64..127, concurrent) ==========
            const int gt = tid - 64;
            float acc = 0.f; int cnt = 0;
            int labprev = 0;
            for (int t = gt; t < TT; t += 64) {
                const int mkv = mask[b * TT + t];
                const int lt = labels[b * TT + t];
                const float mf = (float)mkv;
                acc += scores[((size_t)(b * TT + t)) * NN + lt] * mf;
                if (t > 0) {
                    labprev = labels[b * TT + t - 1];
                    acc += trans[labprev * NN + lt] * mf;
                }
                cnt += mkv;
            }
            #pragma unroll
            for (int off = 16; off; off >>= 1) {
                acc += __shfl_xor_sync(0xffffffffu, acc, off);
                cnt += __shfl_xor_sync(0xffffffffu, cnt, off);
            }
            if ((gt & 31) == 0) { sm.l.redf[gt >> 5] = acc; sm.l.redi[gt >> 5] = cnt; }
            bar2_64();
            if (gt == 0) {
                float a = sm.l.redf[0] + sm.l.redf[1];
                int c = sm.l.redi[0] + sm.l.redi[1];
                g_gold[b] = a + startv[labels[b * TT]] + endv[labels[b * TT + c - 1]];
            }
        }
    } else {
        // ================= VITERBI (128 threads, 2/tag) =====================
        const int b = blockIdx.x - BB;
        const int j = tid >> 1;
        const int h = tid & 1;
        const int i0 = h * 32;

        unsigned mkb[TT/32];
        #pragma unroll
        for (int w = 0; w < TT/32; w++)
            mkb[w] = __ballot_sync(0xffffffffu, mask[b * TT + w * 32 + (tid & 31)] != 0);

        float Tr[32];
        #pragma unroll
        for (int i = 0; i < 32; i++) Tr[i] = trans[(i0 + i) * NN + j];

        const float* srow = scores + (size_t)b * TT * NN + j;
        float alpha = 0.f;
        if (h == 0) { alpha = startv[j] + srow[0]; sm.v.alphaS[0][j] = alpha; }
        float ecur = srow[NN];
        float enext = srow[2 * NN];
        __syncthreads();

        for (int t = 1; t < TT; t++) {
            const int pb = (t - 1) & 1, cb = t & 1;
            float bv[8]; int bx[8];
            #pragma unroll
            for (int c = 0; c < 8; c++) {
                float4 av = *(const float4*)&sm.v.alphaS[pb][i0 + c * 4];
                float v0 = av.x + Tr[c*4+0];
                float v1 = av.y + Tr[c*4+1];
                float v2 = av.z + Tr[c*4+2];
                float v3 = av.w + Tr[c*4+3];
                float cbv = v0; int ci = i0 + c*4;
                if (v1 > cbv) { cbv = v1; ci = i0 + c*4 + 1; }
                if (v2 > cbv) { cbv = v2; ci = i0 + c*4 + 2; }
                if (v3 > cbv) { cbv = v3; ci = i0 + c*4 + 3; }
                bv[c] = cbv; bx[c] = ci;
            }
            float best = bv[0]; int bi = bx[0];
            #pragma unroll
            for (int c = 1; c < 8; c++)
                if (bv[c] > best || (bv[c] == best && bx[c] < bi)) { best = bv[c]; bi = bx[c]; }
            const float vo = __shfl_xor_sync(0xffffffffu, best, 1);
            const int   io = __shfl_xor_sync(0xffffffffu, bi, 1);
            if (vo > best || (vo == best && io < bi)) { best = vo; bi = io; }
            if (h == 0) {
                const int bit = (mkb[t >> 5] >> (t & 31)) & 1;
                sm.v.bp[(t - 1) * NN + j] = (unsigned char)(bit ? bi : j);
                if (bit) alpha = best + ecur;
                sm.v.alphaS[cb][j] = alpha;
            }
            ecur = enext;
            if (t + 2 < TT) enext = srow[(size_t)(t + 2) * NN];
            __syncthreads();
        }
        // backtrace
        if (tid == 0) {
            const int fb = (TT - 1) & 1;
            float bestf = -1e30f; int cur = 0;
            for (int jj = 0; jj < NN; jj++) {
                float v = sm.v.alphaS[fb][jj] + endv[jj];
                if (v > bestf) { bestf = v; cur = jj; }
            }
            sm.v.tag[TT - 1] = cur;
            for (int t = TT - 1; t >= 1; t--) {
                cur = sm.v.bp[(t - 1) * NN + cur];
                sm.v.tag[t - 1] = cur;
            }
        }
        __syncthreads();
        for (int t = tid; t < TT; t += 128) {
            const int bit = (mkb[t >> 5] >> (t & 31)) & 1;
            out_tags[b * TT + t] = (float)(sm.v.tag[t] * bit);
        }
    }
}

// ---------------------------------------------------------------------------
// Loss = mean(log_z - gold)
// ---------------------------------------------------------------------------
__global__ void loss_kernel(float* __restrict__ out_loss) {
    int l = threadIdx.x;  // 32 threads
    float v = (g_logz[l] - g_gold[l]) + (g_logz[l + 32] - g_gold[l + 32]);
    #pragma unroll
    for (int off = 16; off; off >>= 1) v += __shfl_xor_sync(0xffffffffu, v, off);
    if (l == 0) out_loss[0] = v * (1.0f / 64.0f);
}

extern "C" void kernel_launch(void* const* d_in, const int* in_sizes, int n_in,
                              void* d_out, int out_size) {
    const float* X      = (const float*)d_in[0];
    const int*   mask   = (const int*)d_in[1];
    const int*   labels = (const int*)d_in[2];
    const float* W      = (const float*)d_in[3];
    const float* bias   = (const float*)d_in[4];
    const float* trans  = (const float*)d_in[5];
    const float* startv = (const float*)d_in[6];
    const float* endv   = (const float*)d_in[7];
    float* out = (float*)d_out;

    gemm_f32x2_kernel<<<512, 128>>>(X, W, out);
    reduce_kernel<<<SCORES_ELEMS / 4 / 256, 256>>>(bias, mask, out);
    crf_kernel<<<128, 128>>>(out, mask, labels, trans, startv, endv, out + TAGS_OFF);
    loss_kernel<<<1, 32>>>(out + LOSS_OFF);
}